// round 7
// baseline (speedup 1.0000x reference)
#include <cuda_runtime.h>
#include <cstddef>

#define Nn   128
#define Lq   2048
#define NBat 2
#define Tc   32
#define NCH  64          // chunks per batch
#define NBLK 128         // co-resident blocks (1/SM, 148 SMs available)

// Persistent device scratch (zero-initialized at module load)
__device__ float g_AdT[Nn * Nn];             // AdT[m][k] = Ad[k][m]
__device__ float g_Bd[Nn];
__device__ float g_P[Nn * Nn];               // g_P[r][c] = (Ad^32)[r][c]
__device__ float g_lfin[NBat * NCH * Nn];
__device__ float g_s[NBat * NCH * Nn];
__device__ unsigned int g_cnt[2];
__device__ unsigned int g_gen[2];
__device__ unsigned int g_sflag[NBat * NCH]; // generation-tagged ready flags

// Self-resetting grid barrier. Returns this launch's generation (uniform).
__device__ __forceinline__ unsigned gbar(int idx, unsigned* s_gen) {
    __syncthreads();
    if (threadIdx.x == 0) {
        unsigned my = *(volatile unsigned*)&g_gen[idx];
        __threadfence();
        unsigned t = atomicAdd(&g_cnt[idx], 1u);
        if (t == NBLK - 1) {
            g_cnt[idx] = 0;
            __threadfence();
            atomicAdd(&g_gen[idx], 1u);
        } else {
            while (*(volatile unsigned*)&g_gen[idx] == my) __nanosleep(64);
        }
        __threadfence();
        *s_gen = my + 1;
    }
    __syncthreads();
    return *s_gen;
}

__device__ __forceinline__ float scan_dot(const float* __restrict__ a,
                                          const float4* __restrict__ c4) {
    float a0 = 0.f, a1 = 0.f, a2 = 0.f, a3 = 0.f;
    #pragma unroll
    for (int jj = 0; jj < 16; jj++) {
        float4 cv = c4[jj];
        a0 = fmaf(a[4 * jj    ], cv.x, a0);
        a1 = fmaf(a[4 * jj + 1], cv.y, a1);
        a2 = fmaf(a[4 * jj + 2], cv.z, a2);
        a3 = fmaf(a[4 * jj + 3], cv.w, a3);
    }
    return (a0 + a1) + (a2 + a3);
}

// ---------------------------------------------------------------------------
// Single persistent kernel: solve -> phase1 -> Ad^32 rows -> (phase2 on 2
// blocks, pipelined via flags) -> per-chunk rescan with fused y-emission.
// 128 blocks x 256 threads, 67072 B dyn smem (1 block/SM, co-resident).
// ---------------------------------------------------------------------------
__global__ void __launch_bounds__(256, 1)
k_all(const float* __restrict__ A, const float* __restrict__ Bv,
      const float* __restrict__ f, const float* __restrict__ C,
      const float* __restrict__ Dv, float* __restrict__ out) {
    extern __shared__ float sh[];            // solve: A padded (128x129) + 2x128 rhs
    __shared__ float csh[Nn];
    __shared__ float psh[Nn];
    __shared__ float fsh[Tc];
    __shared__ float Csh[Nn];
    __shared__ unsigned s_gen;

    const int bid = blockIdx.x, tid = threadIdx.x;
    const int k = tid & 127, h = tid >> 7, m0 = h * 64;
    const int b = bid >> 6, g = bid & 63;    // chunk coords

    // ===== Stage A: bilinear discretization (forward substitution) =====
    // P = I - 0.5A lower triangular. Block c (h0) solves Ad column c;
    // block 0 (h1) solves Bd. Other h1 halves duplicate harmlessly.
    {
        float* Ash = sh;                     // stride 129 (conflict-free)
        float* x   = sh + Nn * 129;
        for (int idx = tid; idx < Nn * Nn; idx += 256)
            Ash[(idx >> 7) * 129 + (idx & 127)] = A[idx];
        __syncthreads();

        const int i   = k;
        const int col = (h == 1 && bid == 0) ? Nn : bid;
        float* xh = x + h * Nn;
        float r   = (col < Nn) ? ((i == col ? 1.f : 0.f) + 0.5f * Ash[i * 129 + col])
                               : Bv[i];
        float piv = 1.f - 0.5f * Ash[i * 129 + i];
        float acc = 0.f;
        for (int j = 0; j < Nn; j++) {
            if (i == j) xh[j] = (r - acc) / piv;
            __syncthreads();
            if (i > j) acc = fmaf(-0.5f * Ash[i * 129 + j], xh[j], acc);
        }
        if (h == 0) g_AdT[bid * Nn + i] = xh[i];       // AdT[col][i] = Ad[i][col]
        else if (bid == 0) g_Bd[i] = xh[i];
    }
    gbar(0, &s_gen);

    // ===== Stage B: phase 1 — per-chunk zero-init local scan =====
    float a[64];
    #pragma unroll
    for (int j = 0; j < 64; j++) a[j] = g_AdT[(m0 + j) * Nn + k];
    const float bd = g_Bd[k];
    if (tid < Tc) fsh[tid] = f[b * Lq + g * Tc + tid];
    if (h == 0) csh[k] = 0.f;
    __syncthreads();
    {
        const float4* c4 = (const float4*)(csh + m0);
        float cn = 0.f;
        for (int d = 0; d < Tc; d++) {
            float acc = scan_dot(a, c4);
            if (h == 0) acc = fmaf(bd, fsh[d], acc);
            if (h == 1) psh[k] = acc;
            __syncthreads();
            if (h == 0) { cn = acc + psh[k]; csh[k] = cn; }
            __syncthreads();
        }
        if (h == 0) g_lfin[(b * NCH + g) * Nn + k] = cn;
    }

    // ===== Stage C: row bid of Ad^32 via v <- Ad^T v, v0 = e_bid =====
    // (Ad^T)[k][m] = g_AdT[k*128+m]; after 32 steps v[k] = Ad^32[bid][k].
    {
        float w[64];
        #pragma unroll
        for (int j = 0; j < 64; j++) w[j] = g_AdT[k * Nn + m0 + j];
        __syncthreads();
        if (h == 0) csh[k] = (k == bid) ? 1.f : 0.f;
        __syncthreads();
        const float4* c4 = (const float4*)(csh + m0);
        for (int d = 0; d < 32; d++) {
            float acc = scan_dot(w, c4);
            if (h == 1) psh[k] = acc;
            __syncthreads();
            if (h == 0) csh[k] = acc + psh[k];
            __syncthreads();
        }
        if (h == 0) g_P[bid * Nn + k] = csh[k];
    }
    const unsigned G = gbar(1, &s_gen);

    // ===== Stage D: phase 2 on blocks 0,1 (one batch each), publishing
    // entering states with generation-tagged flags as they complete. =====
    if (bid < NBat) {
        float w2[64];
        #pragma unroll
        for (int j = 0; j < 64; j++) w2[j] = g_P[k * Nn + m0 + j]; // Ad^32[k][m]
        if (h == 0) csh[k] = 0.f;
        __syncthreads();
        const float4* c4 = (const float4*)(csh + m0);
        for (int gg = 1; gg < NCH; gg++) {
            float acc = scan_dot(w2, c4);
            if (h == 1) psh[k] = acc;
            __syncthreads();
            if (h == 0) {
                float cn = acc + psh[k] + g_lfin[(bid * NCH + gg - 1) * Nn + k];
                csh[k] = cn;
                g_s[(bid * NCH + gg) * Nn + k] = cn;
            }
            __threadfence();
            __syncthreads();
            if (tid == 0)
                *(volatile unsigned*)&g_sflag[bid * NCH + gg] = G;
        }
    }

    // ===== Stage E: rescan chunk from true entering state, fused emission =====
    #pragma unroll
    for (int j = 0; j < 64; j++) a[j] = g_AdT[(m0 + j) * Nn + k];
    if (tid < Tc) fsh[tid] = f[b * Lq + g * Tc + tid];
    if (tid < Nn) Csh[tid] = C[tid];
    const float D0 = Dv[0];
    if (g == 0) {
        __syncthreads();
        if (h == 0) csh[k] = 0.f;
    } else {
        if (tid == 0) {
            while (*(volatile unsigned*)&g_sflag[b * NCH + g] != G) __nanosleep(64);
            __threadfence();
        }
        __syncthreads();
        if (h == 0) csh[k] = g_s[(b * NCH + g) * Nn + k];
    }
    __syncthreads();

    {
        const float4* c4 = (const float4*)(csh + m0);
        const int wid = tid >> 5, lane = tid & 31;
        float cn = 0.f;
        for (int d = 0; d < Tc; d++) {
            float acc = scan_dot(a, c4);
            if (h == 0) acc = fmaf(bd, fsh[d], acc);
            if (h == 1) psh[k] = acc;
            __syncthreads();
            if (h == 0) { cn = acc + psh[k]; csh[k] = cn; }
            __syncthreads();

            // Emit 128x128 y-block for t = g*Tc + d (64 KB, coalesced STG.128)
            const int t = g * Tc + d;
            const float Df = D0 * fsh[d];
            float4* dst = (float4*)(out + 256 + ((size_t)(b * Lq + t) << 14));
            const float4 cv = ((const float4*)csh)[lane];
            #pragma unroll
            for (int it = 0; it < 16; it++) {
                const int n = it * 8 + wid;     // warp writes full 512B row n
                const float Cn = Csh[n];
                float4 v;
                v.x = fmaf(Cn, cv.x, Df);
                v.y = fmaf(Cn, cv.y, Df);
                v.z = fmaf(Cn, cv.z, Df);
                v.w = fmaf(Cn, cv.w, Df);
                dst[n * 32 + lane] = v;
            }
        }
        if (h == 0 && g == NCH - 1) out[b * Nn + k] = cn;   // c_fin
    }
}

extern "C" void kernel_launch(void* const* d_in, const int* in_sizes, int n_in,
                              void* d_out, int out_size) {
    const float* f  = (const float*)d_in[0];
    const float* A  = (const float*)d_in[1];
    const float* Bv = (const float*)d_in[2];
    const float* C  = (const float*)d_in[3];
    const float* Dv = (const float*)d_in[4];
    float* out = (float*)d_out;

    const int smem = (Nn * 129 + 2 * Nn) * (int)sizeof(float);   // 67072 B
    cudaFuncSetAttribute(k_all, cudaFuncAttributeMaxDynamicSharedMemorySize, smem);
    k_all<<<NBLK, 256, smem>>>(A, Bv, f, C, Dv, out);
}

// round 8
// speedup vs baseline: 1.1737x; 1.1737x over previous
#include <cuda_runtime.h>
#include <cstddef>

#define Nn   128
#define Lq   2048
#define NBat 2
#define Tc   32
#define NCH  64          // chunks per batch
#define NBLK 128         // co-resident blocks (1/SM)
#define NBAR 3

// Persistent device scratch (zero-initialized at module load)
__device__ float g_AdT[Nn * Nn];             // AdT[m][k] = Ad[k][m]
__device__ float g_Bd[Nn];
__device__ float g_P[Nn * Nn];               // g_P[r][c] = (Ad^32)[r][c]
__device__ float g_lfin[NBat * NCH * Nn];
__device__ float g_s[NBat * NCH * Nn];
__device__ float g_c[NBat * Lq * Nn];        // all states (2 MB)
__device__ unsigned int g_cnt[NBAR];
__device__ unsigned int g_gen[NBAR];

// Self-resetting grid barrier (each slot used once per launch; generation
// counter makes it graph-replay-safe without a reset kernel).
__device__ __forceinline__ void gbar(int idx, unsigned* s_tmp) {
    __syncthreads();
    if (threadIdx.x == 0) {
        unsigned my = *(volatile unsigned*)&g_gen[idx];
        __threadfence();
        unsigned t = atomicAdd(&g_cnt[idx], 1u);
        if (t == NBLK - 1) {
            g_cnt[idx] = 0;
            __threadfence();
            atomicAdd(&g_gen[idx], 1u);
        } else {
            while (*(volatile unsigned*)&g_gen[idx] == my) __nanosleep(64);
        }
        __threadfence();
        *s_tmp = my;
    }
    __syncthreads();
}

__device__ __forceinline__ float scan_dot(const float* __restrict__ a,
                                          const float4* __restrict__ c4) {
    float a0 = 0.f, a1 = 0.f, a2 = 0.f, a3 = 0.f;
    #pragma unroll
    for (int jj = 0; jj < 16; jj++) {
        float4 cv = c4[jj];
        a0 = fmaf(a[4 * jj    ], cv.x, a0);
        a1 = fmaf(a[4 * jj + 1], cv.y, a1);
        a2 = fmaf(a[4 * jj + 2], cv.z, a2);
        a3 = fmaf(a[4 * jj + 3], cv.w, a3);
    }
    return (a0 + a1) + (a2 + a3);
}

// ---------------------------------------------------------------------------
// Fused prelude: solve -> phase1 -> Ad^32 rows (barrier-free) -> phase2 ->
// states. 128 blocks x 256 threads, 67072 B dyn smem, 1 block/SM.
// ---------------------------------------------------------------------------
__global__ void __launch_bounds__(256, 1)
k_fused(const float* __restrict__ A, const float* __restrict__ Bv,
        const float* __restrict__ f, float* __restrict__ out) {
    extern __shared__ float sh[];            // A padded (128x129) + 2x128 rhs
    __shared__ float csh[Nn];
    __shared__ float psh[Nn];
    __shared__ float fsh[Tc];
    __shared__ unsigned s_tmp;

    const int bid = blockIdx.x, tid = threadIdx.x;
    const int k = tid & 127, h = tid >> 7, m0 = h * 64;
    const int b = bid >> 6, g = bid & 63;

    // ===== Stage A: forward substitution, P = I - 0.5A (lower tri) =====
    // Block c (h0 half) solves Ad column c; block 0 h1 solves Bd.
    {
        float* Ash = sh;                     // stride 129, conflict-free
        float* x   = sh + Nn * 129;
        for (int idx = tid; idx < Nn * Nn; idx += 256)
            Ash[(idx >> 7) * 129 + (idx & 127)] = A[idx];
        __syncthreads();

        const int i   = k;
        const int col = (h == 1 && bid == 0) ? Nn : bid;
        float* xh = x + h * Nn;
        float r   = (col < Nn) ? ((i == col ? 1.f : 0.f) + 0.5f * Ash[i * 129 + col])
                               : Bv[i];
        float piv = 1.f - 0.5f * Ash[i * 129 + i];
        float acc = 0.f;
        for (int j = 0; j < Nn; j++) {
            if (i == j) xh[j] = (r - acc) / piv;
            __syncthreads();
            if (i > j) acc = fmaf(-0.5f * Ash[i * 129 + j], xh[j], acc);
        }
        if (h == 0) g_AdT[bid * Nn + i] = xh[i];   // AdT[col][i] = Ad[i][col]
        else if (bid == 0) g_Bd[i] = xh[i];
    }
    gbar(0, &s_tmp);

    // ===== Stage B: phase 1 — per-chunk zero-init local scan =====
    float a[64];
    #pragma unroll
    for (int j = 0; j < 64; j++) a[j] = g_AdT[(m0 + j) * Nn + k];
    const float bd = g_Bd[k];
    if (tid < Tc) fsh[tid] = f[b * Lq + g * Tc + tid];
    if (h == 0) csh[k] = 0.f;
    __syncthreads();
    {
        const float4* c4 = (const float4*)(csh + m0);
        float cn = 0.f;
        for (int d = 0; d < Tc; d++) {
            float acc = scan_dot(a, c4);
            if (h == 0) acc = fmaf(bd, fsh[d], acc);
            if (h == 1) psh[k] = acc;
            __syncthreads();
            if (h == 0) { cn = acc + psh[k]; csh[k] = cn; }
            __syncthreads();
        }
        if (h == 0) g_lfin[(b * NCH + g) * Nn + k] = cn;
    }

    // ===== Stage C: row bid of Ad^32 via v <- Ad^T v, v0 = e_bid =====
    {
        float w[64];
        #pragma unroll
        for (int j = 0; j < 64; j++) w[j] = g_AdT[k * Nn + m0 + j];  // Ad[m][k]
        __syncthreads();
        if (h == 0) csh[k] = (k == bid) ? 1.f : 0.f;
        __syncthreads();
        const float4* c4 = (const float4*)(csh + m0);
        for (int d = 0; d < 32; d++) {
            float acc = scan_dot(w, c4);
            if (h == 1) psh[k] = acc;
            __syncthreads();
            if (h == 0) csh[k] = acc + psh[k];
            __syncthreads();
        }
        if (h == 0) g_P[bid * Nn + k] = csh[k];    // Ad^32[bid][k]
    }
    gbar(1, &s_tmp);

    // ===== Stage D: phase 2 on blocks 0,1: s_{g+1} = Ad^32 s_g + lfin_g =====
    if (bid < NBat) {
        float w2[64];
        #pragma unroll
        for (int j = 0; j < 64; j++) w2[j] = g_P[k * Nn + m0 + j];   // Ad^32[k][m]
        if (h == 0) { csh[k] = 0.f; g_s[(bid * NCH) * Nn + k] = 0.f; }
        __syncthreads();
        const float4* c4 = (const float4*)(csh + m0);
        for (int gg = 1; gg < NCH; gg++) {
            float acc = scan_dot(w2, c4);
            if (h == 1) psh[k] = acc;
            __syncthreads();
            if (h == 0) {
                float cn = acc + psh[k] + g_lfin[(bid * NCH + gg - 1) * Nn + k];
                csh[k] = cn;
                g_s[(bid * NCH + gg) * Nn + k] = cn;
            }
            __syncthreads();
        }
    }
    gbar(2, &s_tmp);

    // ===== Stage E: rescan chunk from true entering state; write states =====
    {
        if (tid < Tc) fsh[tid] = f[b * Lq + g * Tc + tid];
        if (h == 0) csh[k] = g_s[(b * NCH + g) * Nn + k];
        __syncthreads();
        const float4* c4 = (const float4*)(csh + m0);
        float cn = 0.f;
        for (int d = 0; d < Tc; d++) {
            float acc = scan_dot(a, c4);
            if (h == 0) acc = fmaf(bd, fsh[d], acc);
            if (h == 1) psh[k] = acc;
            __syncthreads();
            if (h == 0) {
                cn = acc + psh[k];
                csh[k] = cn;
                g_c[(size_t)(b * Lq + g * Tc + d) * Nn + k] = cn;
            }
            __syncthreads();
        }
        if (h == 0 && g == NCH - 1) out[b * Nn + k] = cn;   // c_fin
    }
}

// ---------------------------------------------------------------------------
// Broadcast: y[b,t,n,k] = C[n]*c[b,t,k] + D*f[b,t].  4096 blocks, one (b,t).
// Pure-BW store engine (proven config).
// ---------------------------------------------------------------------------
__global__ void k_bcast(const float* __restrict__ C, const float* __restrict__ Dv,
                        const float* __restrict__ f, float* __restrict__ out) {
    const int bt = blockIdx.x;
    const int tid = threadIdx.x, wid = tid >> 5, lane = tid & 31;
    __shared__ float csh[Nn];
    __shared__ float Csh[Nn];
    if (tid < Nn) {
        csh[tid] = g_c[(size_t)bt * Nn + tid];
        Csh[tid] = C[tid];
    }
    const float Df = Dv[0] * f[bt];
    __syncthreads();

    const float4 cv = ((const float4*)csh)[lane];
    float4* dst = (float4*)(out + 256 + ((size_t)bt << 14));
    #pragma unroll
    for (int it = 0; it < 16; it++) {
        const int n = it * 8 + wid;          // warp writes one full 512B row
        const float Cn = Csh[n];
        float4 v;
        v.x = fmaf(Cn, cv.x, Df);
        v.y = fmaf(Cn, cv.y, Df);
        v.z = fmaf(Cn, cv.z, Df);
        v.w = fmaf(Cn, cv.w, Df);
        dst[n * 32 + lane] = v;
    }
}

extern "C" void kernel_launch(void* const* d_in, const int* in_sizes, int n_in,
                              void* d_out, int out_size) {
    const float* f  = (const float*)d_in[0];
    const float* A  = (const float*)d_in[1];
    const float* Bv = (const float*)d_in[2];
    const float* C  = (const float*)d_in[3];
    const float* Dv = (const float*)d_in[4];
    float* out = (float*)d_out;

    const int smem = (Nn * 129 + 2 * Nn) * (int)sizeof(float);   // 67072 B
    cudaFuncSetAttribute(k_fused, cudaFuncAttributeMaxDynamicSharedMemorySize, smem);
    k_fused<<<NBLK, 256, smem>>>(A, Bv, f, out);
    k_bcast<<<NBat * Lq, 256>>>(C, Dv, f, out);
}